// round 12
// baseline (speedup 1.0000x reference)
#include <cuda_runtime.h>
#include <cuda_bf16.h>
#include <cstdint>

#define DIN        118
#define DOUT       64
#define TILE       32
#define THREADS    128
#define HSTRIDE    72        // floats per h row (padding vs bank conflicts)
#define XROW_BYTES 472       // 118 * 4
#define XTILE_B    (TILE * XROW_BYTES)   // 15104, 16B-multiple
#define NSTAGE     2

// dynamic smem layout (bytes)
#define SM_H      0                       // f32  [32][72]            = 9216
#define SM_BATCH  9216                    // int  [32] clamped        = 128
#define SM_MBAR   9344                    // 2 x 8B mbarriers         = 16
#define SM_BSTG   9360                    // raw batch staging 2x128  = 256
#define SM_STG    9616                    // f32 staging 2 x 15104 (16B aligned)
#define SMEM_TOTAL (SM_STG + NSTAGE * XTILE_B)   // 39824  (5 CTAs = 199 KB)

// segment-sum scratch (consumed & re-zeroed by normalize -> graph-replay safe)
#define SCRATCH_CAP (1 << 20)             // 4 MB: supports nSeg <= 16384
__device__ float g_scratch[SCRATCH_CAP];

// ---------------- helpers ----------------

__device__ __forceinline__ uint32_t smem_to_u32(const void* p) {
    uint32_t a;
    asm("{ .reg .u64 t; cvta.to.shared.u64 t, %1; cvt.u32.u64 %0, t; }"
        : "=r"(a) : "l"(p));
    return a;
}

#define CVT_BF16X2(result, lo, hi) \
    asm("cvt.rn.satfinite.bf16x2.f32 %0, %1, %2;" : "=r"(result) : "f"(hi), "f"(lo))

#define MBARRIER_INIT(mbar, count) \
    asm volatile("mbarrier.init.shared.b64 [%0], %1;" \
                 :: "r"((uint32_t)(mbar)), "r"((uint32_t)(count)) : "memory")

#define MBARRIER_EXPECT_TX(mbar, tx_bytes) \
    asm volatile("mbarrier.arrive.expect_tx.shared.b64 _, [%0], %1;" \
                 :: "r"((uint32_t)(mbar)), "r"((uint32_t)(tx_bytes)) : "memory")

#define MBARRIER_WAIT_PARITY(mbar, parity) do {                                   \
    uint32_t _m = (uint32_t)(mbar);                                               \
    uint32_t _p = (uint32_t)(parity);                                             \
    uint32_t _done;                                                               \
    asm volatile("{\n\t.reg .pred p;\n\t"                                         \
        "mbarrier.try_wait.parity.acquire.cta.shared::cta.b64 p, [%1], %2;\n\t"   \
        "selp.b32 %0, 1, 0, p;\n\t}"                                              \
        : "=r"(_done) : "r"(_m), "r"(_p) : "memory");                             \
    if (!_done) {                                                                 \
        asm volatile("{\n\t.reg .pred P1;\n\t"                                    \
            "WAIT_LOOP_%=:\n\t"                                                   \
            "mbarrier.try_wait.parity.acquire.cta.shared::cta.b64 P1, [%0], %1, 0x989680;\n\t" \
            "@P1 bra.uni WAIT_DONE_%=;\n\t"                                       \
            "bra.uni WAIT_LOOP_%=;\n\t"                                           \
            "WAIT_DONE_%=:\n\t}"                                                  \
            :: "r"(_m), "r"(_p) : "memory");                                      \
    }                                                                             \
} while (0)

// single bulk async copy: global -> shared, completion via mbarrier tx-bytes
#define CP_BULK(dst_smem, src_gmem, nbytes, mbar) \
    asm volatile("cp.async.bulk.shared::cluster.global.mbarrier::complete_tx::bytes " \
                 "[%0], [%1], %2, [%3];" \
                 :: "r"((uint32_t)(dst_smem)), "l"(src_gmem), \
                    "r"((uint32_t)(nbytes)), "r"((uint32_t)(mbar)) : "memory")

__device__ __forceinline__ void mma16816(float* d, uint32_t a0, uint32_t a1, uint32_t a2,
                                         uint32_t a3, uint32_t b0, uint32_t b1) {
    asm volatile("mma.sync.aligned.m16n8k16.row.col.f32.bf16.bf16.f32 "
                 "{%0,%1,%2,%3}, {%4,%5,%6,%7}, {%8,%9}, {%0,%1,%2,%3};"
                 : "+f"(d[0]), "+f"(d[1]), "+f"(d[2]), "+f"(d[3])
                 : "r"(a0), "r"(a1), "r"(a2), "r"(a3), "r"(b0), "r"(b1));
}

// issue bulk copies (x tile + batch ids) for one tile into staging buffer `buf`
__device__ __forceinline__ void issue_tile(const char* xbase, const char* bbase,
                                           uint32_t smem_u, int buf,
                                           int tile, int nAtoms)
{
    int valid = nAtoms - tile * TILE;
    if (valid > TILE) valid = TILE;
    const uint32_t xb16 = (uint32_t)(valid * XROW_BYTES) & ~15u;
    const uint32_t bb16 = (uint32_t)(valid * 4) & ~15u;
    const uint32_t mb = smem_u + SM_MBAR + 8u * (uint32_t)buf;
    MBARRIER_EXPECT_TX(mb, xb16 + bb16);
    CP_BULK(smem_u + SM_STG + buf * XTILE_B,
            xbase + (size_t)tile * XTILE_B, xb16, mb);
    if (bb16)
        CP_BULK(smem_u + SM_BSTG + buf * 128,
                bbase + (size_t)tile * TILE * 4, bb16, mb);
}

// ---------------- main fused kernel ----------------

__global__ void __launch_bounds__(THREADS, 5)
fused_embed_segsum_kernel(const float* __restrict__ x,
                          const float* __restrict__ W,
                          const float* __restrict__ bias_v,
                          const int*   __restrict__ batch,    // int32
                          int nAtoms, int nTiles, int nSeg)
{
    extern __shared__ char smem[];
    const uint32_t smem_u = smem_to_u32(smem);
    const int tid  = threadIdx.x;
    const int wid  = tid >> 5;    // 0..3
    const int lane = tid & 31;

    float* h_sm     = reinterpret_cast<float*>(smem + SM_H);
    int*   batch_sm = reinterpret_cast<int*>(smem + SM_BATCH);
    const char* xbase = reinterpret_cast<const char*>(x);
    const char* bbase = reinterpret_cast<const char*>(batch);
    float* out_s = g_scratch;

    int segCap = nSeg;
    if (segCap * DOUT > SCRATCH_CAP) segCap = SCRATCH_CAP / DOUT;

    // ---- init mbarriers; issue copy of first tile into buf 0 ----
    if (tid == 0) {
        MBARRIER_INIT(smem_u + SM_MBAR, 1);
        MBARRIER_INIT(smem_u + SM_MBAR + 8, 1);
    }
    __syncthreads();

    const int t0 = blockIdx.x;
    if (tid == 0 && t0 < nTiles)
        issue_tile(xbase, bbase, smem_u, 0, t0, nAtoms);

    // warp tiling: rows (wid&1)*16, cols (wid>>1)*32
    const int m0    = (wid & 1) * 16;
    const int nbase = (wid >> 1) * 32;

    // ---- W fragments straight from global (canonical m16n8k16 B layout) ----
    uint32_t bf[8][8];   // [ks][j*2 + {lo,hi}]
    {
        const int kcw = 2 * (lane & 3);
        #pragma unroll
        for (int ks = 0; ks < 8; ks++) {
            const int k0 = 16 * ks + kcw;
            const int k1 = k0 + 8;
            #pragma unroll
            for (int j = 0; j < 4; j++) {
                const int n = nbase + j * 8 + (lane >> 2);
                const float* wr = W + (size_t)n * DIN;
                uint32_t lo = 0, hi = 0;
                if (k0 < DIN) { float2 v = *reinterpret_cast<const float2*>(wr + k0); CVT_BF16X2(lo, v.x, v.y); }
                if (k1 < DIN) { float2 v = *reinterpret_cast<const float2*>(wr + k1); CVT_BF16X2(hi, v.x, v.y); }
                bf[ks][j * 2]     = lo;
                bf[ks][j * 2 + 1] = hi;
            }
        }
    }

    // A-fragment row/col bases (row-major A, m16n8k16)
    const int rA0 = m0 + (lane >> 2);
    const int rA1 = rA0 + 8;
    const int kc  = 2 * (lane & 3);
    const float* bias_l = bias_v + nbase + 2 * (lane & 3);   // epilogue bias base

    int wrap = 0;
    int it = 0;
    for (int t = t0; t < nTiles; t += gridDim.x, it++) {
        const int row0 = t * TILE;
        int valid = nAtoms - row0;
        if (valid > TILE) valid = TILE;
        const int buf = it & 1;
        const float* stg_f = reinterpret_cast<const float*>(smem + SM_STG + buf * XTILE_B);
        const int* bstg = reinterpret_cast<const int*>(smem + SM_BSTG + buf * 128);

        // 1) issue copy of NEXT tile into the other buffer (drained last iteration)
        const int tn = t + gridDim.x;
        if (tid == 0 && tn < nTiles)
            issue_tile(xbase, bbase, smem_u, buf ^ 1, tn, nAtoms);

        // 2) wait for CURRENT tile's copies (per-thread acquire: no CTA sync needed
        //    before GEMM). Stage batch ids; rare-tail patch keeps its own sync.
        MBARRIER_WAIT_PARITY(smem_u + SM_MBAR + 8u * (uint32_t)buf, (it >> 1) & 1);
        if (tid < TILE) {
            int v = 0;
            if (tid < valid) {
                v = (((tid + 1) * 4) <= ((valid * 4) & ~15)) ? bstg[tid]
                                                             : batch[row0 + tid];
                if (v < 0) v = 0;
                if (v >= segCap) v = segCap - 1;
            }
            batch_sm[tid] = v;
        }
        if (valid * XROW_BYTES & 15) {        // uniform branch; never taken for N%32==0
            if (tid == 0) {
                const int off = (valid * XROW_BYTES) & ~15;
                float2 v = *reinterpret_cast<const float2*>(
                    xbase + (size_t)row0 * XROW_BYTES + off);
                *reinterpret_cast<float2*>(const_cast<float*>(stg_f) + off / 4) = v;
            }
            __syncthreads();
        }

        // 3) GEMM: A fragments from f32 staging (LDS.64 + cvt), B from regs
        const bool rv0 = rA0 < valid;
        const bool rv1 = rA1 < valid;
        const float* pA0 = stg_f + rA0 * DIN;
        const float* pA1 = stg_f + rA1 * DIN;

        float acc[4][4];
        #pragma unroll
        for (int nt = 0; nt < 4; nt++)
            #pragma unroll
            for (int i = 0; i < 4; i++) acc[nt][i] = 0.0f;

        #pragma unroll
        for (int ks = 0; ks < 8; ks++) {
            const int k0 = 16 * ks + kc;
            const int k1 = k0 + 8;
            uint32_t a0 = 0, a1 = 0, a2 = 0, a3 = 0;
            if (rv0 && k0 < DIN) { float2 v = *reinterpret_cast<const float2*>(pA0 + k0); CVT_BF16X2(a0, v.x, v.y); }
            if (rv1 && k0 < DIN) { float2 v = *reinterpret_cast<const float2*>(pA1 + k0); CVT_BF16X2(a1, v.x, v.y); }
            if (rv0 && k1 < DIN) { float2 v = *reinterpret_cast<const float2*>(pA0 + k1); CVT_BF16X2(a2, v.x, v.y); }
            if (rv1 && k1 < DIN) { float2 v = *reinterpret_cast<const float2*>(pA1 + k1); CVT_BF16X2(a3, v.x, v.y); }
            mma16816(acc[0], a0, a1, a2, a3, bf[ks][0], bf[ks][1]);
            mma16816(acc[1], a0, a1, a2, a3, bf[ks][2], bf[ks][3]);
            mma16816(acc[2], a0, a1, a2, a3, bf[ks][4], bf[ks][5]);
            mma16816(acc[3], a0, a1, a2, a3, bf[ks][6], bf[ks][7]);
        }

        // 4) bias + relu -> h_sm  (bias via L1-hit loads; saves 8 live regs)
        {
            const int rbase = m0 + (lane >> 2);
            const int c0 = nbase + 2 * (lane & 3);
            #pragma unroll
            for (int nt = 0; nt < 4; nt++) {
                const float2 bvn = __ldg(reinterpret_cast<const float2*>(bias_l + nt * 8));
                float2 h0, h1;
                h0.x = fmaxf(acc[nt][0] + bvn.x, 0.0f);
                h0.y = fmaxf(acc[nt][1] + bvn.y, 0.0f);
                h1.x = fmaxf(acc[nt][2] + bvn.x, 0.0f);
                h1.y = fmaxf(acc[nt][3] + bvn.y, 0.0f);
                *reinterpret_cast<float2*>(h_sm + rbase * HSTRIDE + nt * 8 + c0) = h0;
                *reinterpret_cast<float2*>(h_sm + (rbase + 8) * HSTRIDE + nt * 8 + c0) = h1;
            }
        }
        __syncthreads();

        // 5) sorted-segment run-length reduction into g_scratch:
        //    4 warps; warp w handles atoms [w*8, w*8+8); each lane owns 2 cols.
        {
            const int o2 = 2 * lane;
            const int cbase = wid * 8;
            if (cbase < valid) {
                int cend = cbase + 8;
                if (cend > valid) cend = valid;
                int cur = batch_sm[cbase];
                float2 acc2 = make_float2(0.0f, 0.0f);
                for (int c = cbase; c < cend; c++) {
                    const int seg = batch_sm[c];      // LDS broadcast, warp-uniform
                    if (seg != cur) {                 // warp-uniform branch
                        atomicAdd(out_s + (size_t)cur * DOUT + o2,     acc2.x);
                        atomicAdd(out_s + (size_t)cur * DOUT + o2 + 1, acc2.y);
                        acc2.x = 0.0f; acc2.y = 0.0f;
                        cur = seg;
                    }
                    float2 hv = *reinterpret_cast<const float2*>(h_sm + c * HSTRIDE + o2);
                    acc2.x += hv.x;
                    acc2.y += hv.y;
                }
                atomicAdd(out_s + (size_t)cur * DOUT + o2,     acc2.x);
                atomicAdd(out_s + (size_t)cur * DOUT + o2 + 1, acc2.y);
            }
        }
        __syncthreads();   // h_sm / batch_sm reuse; staging(buf) rearm next iter
    }
}

// ---------------- relu + row-max normalize (consumes & re-zeroes scratch) ----------------
// 128 threads/block; each 16-lane half-warp owns one graph (64 f32 = 16 x float4).

__global__ void normalize_kernel(float* __restrict__ out, int nSeg)
{
    const int half = threadIdx.x >> 4;           // 0..7 half-warps per block
    const int hl   = threadIdx.x & 15;
    const int g    = blockIdx.x * 8 + half;
    if (g >= nSeg) return;
    const size_t base = (size_t)g * DOUT + hl * 4;
    float4 v = *reinterpret_cast<float4*>(g_scratch + base);
    *reinterpret_cast<float4*>(g_scratch + base) = make_float4(0.f, 0.f, 0.f, 0.f);
    v.x = fmaxf(v.x, 0.0f); v.y = fmaxf(v.y, 0.0f);
    v.z = fmaxf(v.z, 0.0f); v.w = fmaxf(v.w, 0.0f);
    float m = fmaxf(fmaxf(v.x, v.y), fmaxf(v.z, v.w));
    #pragma unroll
    for (int off = 8; off > 0; off >>= 1)
        m = fmaxf(m, __shfl_xor_sync(0xffffffff, m, off));
    float4 r;
    r.x = v.x / m; r.y = v.y / m; r.z = v.z / m; r.w = v.w / m;
    *reinterpret_cast<float4*>(out + base) = r;
}

// ---------------- launch ----------------

extern "C" void kernel_launch(void* const* d_in, const int* in_sizes, int n_in,
                              void* d_out, int out_size)
{
    const float* x     = (const float*)d_in[0];
    const float* W     = (const float*)d_in[1];
    const float* b     = (const float*)d_in[2];
    const int*   batch = (const int*)d_in[3];
    float* out = (float*)d_out;

    const int nAtoms = in_sizes[0] / DIN;
    const int nSeg   = out_size / DOUT;
    const int nTiles = (nAtoms + TILE - 1) / TILE;

    cudaFuncSetAttribute(fused_embed_segsum_kernel,
                         cudaFuncAttributeMaxDynamicSharedMemorySize, SMEM_TOTAL);

    int grid = 740;                    // 5 CTAs/SM, persistent
    if (grid > nTiles) grid = nTiles;

    fused_embed_segsum_kernel<<<grid, THREADS, SMEM_TOTAL>>>(
        x, W, b, batch, nAtoms, nTiles, nSeg);
    normalize_kernel<<<(nSeg + 7) / 8, 128>>>(out, nSeg);
}

// round 13
// speedup vs baseline: 1.0955x; 1.0955x over previous
#include <cuda_runtime.h>
#include <cuda_bf16.h>
#include <cstdint>

#define DIN        118
#define DOUT       64
#define TILE       32
#define THREADS    128
#define HSTRIDE    72        // floats per h row (padding vs bank conflicts)
#define XROW_BYTES 472       // 118 * 4
#define XTILE_B    (TILE * XROW_BYTES)   // 15104, 16B-multiple
#define NSTAGE     2
#define HTILE_B    (TILE * HSTRIDE * 4)  // 9216

// dynamic smem layout (bytes)
#define SM_H      0                       // f32 [2][32][72]          = 18432
#define SM_BATCH  18432                   // int [2][32] clamped      = 256
#define SM_MBAR   18688                   // 2 x 8B mbarriers         = 16
#define SM_BSTG   18704                   // raw batch staging 2x128  = 256
#define SM_STG    18960                   // f32 staging 2 x 15104 (16B aligned)
#define SMEM_TOTAL (SM_STG + NSTAGE * XTILE_B)   // 49168  (4 CTAs = 196.7 KB)

// segment-sum scratch (consumed & re-zeroed by normalize -> graph-replay safe)
#define SCRATCH_CAP (1 << 20)             // 4 MB: supports nSeg <= 16384
__device__ float g_scratch[SCRATCH_CAP];

// ---------------- helpers ----------------

__device__ __forceinline__ uint32_t smem_to_u32(const void* p) {
    uint32_t a;
    asm("{ .reg .u64 t; cvta.to.shared.u64 t, %1; cvt.u32.u64 %0, t; }"
        : "=r"(a) : "l"(p));
    return a;
}

#define CVT_BF16X2(result, lo, hi) \
    asm("cvt.rn.satfinite.bf16x2.f32 %0, %1, %2;" : "=r"(result) : "f"(hi), "f"(lo))

#define MBARRIER_INIT(mbar, count) \
    asm volatile("mbarrier.init.shared.b64 [%0], %1;" \
                 :: "r"((uint32_t)(mbar)), "r"((uint32_t)(count)) : "memory")

#define MBARRIER_EXPECT_TX(mbar, tx_bytes) \
    asm volatile("mbarrier.arrive.expect_tx.shared.b64 _, [%0], %1;" \
                 :: "r"((uint32_t)(mbar)), "r"((uint32_t)(tx_bytes)) : "memory")

#define MBARRIER_WAIT_PARITY(mbar, parity) do {                                   \
    uint32_t _m = (uint32_t)(mbar);                                               \
    uint32_t _p = (uint32_t)(parity);                                             \
    uint32_t _done;                                                               \
    asm volatile("{\n\t.reg .pred p;\n\t"                                         \
        "mbarrier.try_wait.parity.acquire.cta.shared::cta.b64 p, [%1], %2;\n\t"   \
        "selp.b32 %0, 1, 0, p;\n\t}"                                              \
        : "=r"(_done) : "r"(_m), "r"(_p) : "memory");                             \
    if (!_done) {                                                                 \
        asm volatile("{\n\t.reg .pred P1;\n\t"                                    \
            "WAIT_LOOP_%=:\n\t"                                                   \
            "mbarrier.try_wait.parity.acquire.cta.shared::cta.b64 P1, [%0], %1, 0x989680;\n\t" \
            "@P1 bra.uni WAIT_DONE_%=;\n\t"                                       \
            "bra.uni WAIT_LOOP_%=;\n\t"                                           \
            "WAIT_DONE_%=:\n\t}"                                                  \
            :: "r"(_m), "r"(_p) : "memory");                                      \
    }                                                                             \
} while (0)

// single bulk async copy: global -> shared, completion via mbarrier tx-bytes
#define CP_BULK(dst_smem, src_gmem, nbytes, mbar) \
    asm volatile("cp.async.bulk.shared::cluster.global.mbarrier::complete_tx::bytes " \
                 "[%0], [%1], %2, [%3];" \
                 :: "r"((uint32_t)(dst_smem)), "l"(src_gmem), \
                    "r"((uint32_t)(nbytes)), "r"((uint32_t)(mbar)) : "memory")

__device__ __forceinline__ void mma16816(float* d, uint32_t a0, uint32_t a1, uint32_t a2,
                                         uint32_t a3, uint32_t b0, uint32_t b1) {
    asm volatile("mma.sync.aligned.m16n8k16.row.col.f32.bf16.bf16.f32 "
                 "{%0,%1,%2,%3}, {%4,%5,%6,%7}, {%8,%9}, {%0,%1,%2,%3};"
                 : "+f"(d[0]), "+f"(d[1]), "+f"(d[2]), "+f"(d[3])
                 : "r"(a0), "r"(a1), "r"(a2), "r"(a3), "r"(b0), "r"(b1));
}

// issue bulk copies (x tile + batch ids) for one tile into staging buffer `buf`
__device__ __forceinline__ void issue_tile(const char* xbase, const char* bbase,
                                           uint32_t smem_u, int buf,
                                           int tile, int nAtoms)
{
    int valid = nAtoms - tile * TILE;
    if (valid > TILE) valid = TILE;
    const uint32_t xb16 = (uint32_t)(valid * XROW_BYTES) & ~15u;
    const uint32_t bb16 = (uint32_t)(valid * 4) & ~15u;
    const uint32_t mb = smem_u + SM_MBAR + 8u * (uint32_t)buf;
    MBARRIER_EXPECT_TX(mb, xb16 + bb16);
    CP_BULK(smem_u + SM_STG + buf * XTILE_B,
            xbase + (size_t)tile * XTILE_B, xb16, mb);
    if (bb16)
        CP_BULK(smem_u + SM_BSTG + buf * 128,
                bbase + (size_t)tile * TILE * 4, bb16, mb);
}

// ---------------- main fused kernel ----------------

__global__ void __launch_bounds__(THREADS, 4)
fused_embed_segsum_kernel(const float* __restrict__ x,
                          const float* __restrict__ W,
                          const float* __restrict__ bias_v,
                          const int*   __restrict__ batch,    // int32
                          int nAtoms, int nTiles, int nSeg)
{
    extern __shared__ char smem[];
    const uint32_t smem_u = smem_to_u32(smem);
    const int tid  = threadIdx.x;
    const int wid  = tid >> 5;    // 0..3
    const int lane = tid & 31;

    const char* xbase = reinterpret_cast<const char*>(x);
    const char* bbase = reinterpret_cast<const char*>(batch);
    float* out_s = g_scratch;

    int segCap = nSeg;
    if (segCap * DOUT > SCRATCH_CAP) segCap = SCRATCH_CAP / DOUT;

    // ---- init mbarriers; issue copy of first tile into buf 0 ----
    if (tid == 0) {
        MBARRIER_INIT(smem_u + SM_MBAR, 1);
        MBARRIER_INIT(smem_u + SM_MBAR + 8, 1);
    }
    __syncthreads();

    const int t0 = blockIdx.x;
    if (tid == 0 && t0 < nTiles)
        issue_tile(xbase, bbase, smem_u, 0, t0, nAtoms);

    // warp tiling: rows (wid&1)*16, cols (wid>>1)*32
    const int m0    = (wid & 1) * 16;
    const int nbase = (wid >> 1) * 32;

    // ---- W fragments straight from global (canonical m16n8k16 B layout) ----
    uint32_t bf[8][8];   // [ks][j*2 + {lo,hi}]
    {
        const int kcw = 2 * (lane & 3);
        #pragma unroll
        for (int ks = 0; ks < 8; ks++) {
            const int k0 = 16 * ks + kcw;
            const int k1 = k0 + 8;
            #pragma unroll
            for (int j = 0; j < 4; j++) {
                const int n = nbase + j * 8 + (lane >> 2);
                const float* wr = W + (size_t)n * DIN;
                uint32_t lo = 0, hi = 0;
                if (k0 < DIN) { float2 v = *reinterpret_cast<const float2*>(wr + k0); CVT_BF16X2(lo, v.x, v.y); }
                if (k1 < DIN) { float2 v = *reinterpret_cast<const float2*>(wr + k1); CVT_BF16X2(hi, v.x, v.y); }
                bf[ks][j * 2]     = lo;
                bf[ks][j * 2 + 1] = hi;
            }
        }
    }

    // per-lane bias for epilogue cols nbase + nt*8 + 2*(lane&3) + {0,1}
    float2 bv[4];
    {
        const int c0 = nbase + 2 * (lane & 3);
        #pragma unroll
        for (int nt = 0; nt < 4; nt++)
            bv[nt] = *reinterpret_cast<const float2*>(bias_v + nt * 8 + c0);
    }

    // A-fragment row/col bases (row-major A, m16n8k16)
    const int rA0 = m0 + (lane >> 2);
    const int rA1 = rA0 + 8;
    const int kc  = 2 * (lane & 3);

    int it = 0;
    for (int t = t0; t < nTiles; t += gridDim.x, it++) {
        const int row0 = t * TILE;
        int valid = nAtoms - row0;
        if (valid > TILE) valid = TILE;
        const int buf = it & 1;
        float* h_sm     = reinterpret_cast<float*>(smem + SM_H + buf * HTILE_B);
        int*   batch_sm = reinterpret_cast<int*>(smem + SM_BATCH + buf * 128);
        const float* stg_f = reinterpret_cast<const float*>(smem + SM_STG + buf * XTILE_B);
        const int* bstg = reinterpret_cast<const int*>(smem + SM_BSTG + buf * 128);

        // 1) issue copy of NEXT tile into the other buffer (GEMM reads of it
        //    finished before the sync we passed last iteration)
        const int tn = t + gridDim.x;
        if (tid == 0 && tn < nTiles)
            issue_tile(xbase, bbase, smem_u, buf ^ 1, tn, nAtoms);

        // 2) wait for CURRENT tile's copies (per-thread acquire); stage batch ids
        MBARRIER_WAIT_PARITY(smem_u + SM_MBAR + 8u * (uint32_t)buf, (it >> 1) & 1);
        if (tid < TILE) {
            int v = 0;
            if (tid < valid) {
                v = (((tid + 1) * 4) <= ((valid * 4) & ~15)) ? bstg[tid]
                                                             : batch[row0 + tid];
                if (v < 0) v = 0;
                if (v >= segCap) v = segCap - 1;
            }
            batch_sm[tid] = v;
        }
        if (valid * XROW_BYTES & 15) {        // uniform; never taken when N%32==0
            if (tid == 0) {
                const int off = (valid * XROW_BYTES) & ~15;
                float2 v = *reinterpret_cast<const float2*>(
                    xbase + (size_t)row0 * XROW_BYTES + off);
                *reinterpret_cast<float2*>(const_cast<float*>(stg_f) + off / 4) = v;
            }
            __syncthreads();
        }

        // 3) GEMM: A fragments from f32 staging (LDS.64 + cvt), B from regs
        const bool rv0 = rA0 < valid;
        const bool rv1 = rA1 < valid;
        const float* pA0 = stg_f + rA0 * DIN;
        const float* pA1 = stg_f + rA1 * DIN;

        float acc[4][4];
        #pragma unroll
        for (int nt = 0; nt < 4; nt++)
            #pragma unroll
            for (int i = 0; i < 4; i++) acc[nt][i] = 0.0f;

        #pragma unroll
        for (int ks = 0; ks < 8; ks++) {
            const int k0 = 16 * ks + kc;
            const int k1 = k0 + 8;
            uint32_t a0 = 0, a1 = 0, a2 = 0, a3 = 0;
            if (rv0 && k0 < DIN) { float2 v = *reinterpret_cast<const float2*>(pA0 + k0); CVT_BF16X2(a0, v.x, v.y); }
            if (rv1 && k0 < DIN) { float2 v = *reinterpret_cast<const float2*>(pA1 + k0); CVT_BF16X2(a1, v.x, v.y); }
            if (rv0 && k1 < DIN) { float2 v = *reinterpret_cast<const float2*>(pA0 + k1); CVT_BF16X2(a2, v.x, v.y); }
            if (rv1 && k1 < DIN) { float2 v = *reinterpret_cast<const float2*>(pA1 + k1); CVT_BF16X2(a3, v.x, v.y); }
            mma16816(acc[0], a0, a1, a2, a3, bf[ks][0], bf[ks][1]);
            mma16816(acc[1], a0, a1, a2, a3, bf[ks][2], bf[ks][3]);
            mma16816(acc[2], a0, a1, a2, a3, bf[ks][4], bf[ks][5]);
            mma16816(acc[3], a0, a1, a2, a3, bf[ks][6], bf[ks][7]);
        }

        // 4) bias + relu -> h_sm[buf]
        {
            const int rbase = m0 + (lane >> 2);
            const int c0 = nbase + 2 * (lane & 3);
            #pragma unroll
            for (int nt = 0; nt < 4; nt++) {
                float2 h0, h1;
                h0.x = fmaxf(acc[nt][0] + bv[nt].x, 0.0f);
                h0.y = fmaxf(acc[nt][1] + bv[nt].y, 0.0f);
                h1.x = fmaxf(acc[nt][2] + bv[nt].x, 0.0f);
                h1.y = fmaxf(acc[nt][3] + bv[nt].y, 0.0f);
                *reinterpret_cast<float2*>(h_sm + rbase * HSTRIDE + nt * 8 + c0) = h0;
                *reinterpret_cast<float2*>(h_sm + (rbase + 8) * HSTRIDE + nt * 8 + c0) = h1;
            }
        }
        __syncthreads();   // the ONLY per-tile sync: h/batch ready for all warps;
                           // also orders prior-iteration consumers vs next overwrites

        // 5) sorted-segment run-length reduction into g_scratch:
        //    4 warps; warp w handles atoms [w*8, w*8+8); each lane owns 2 cols.
        //    h values preloaded (independent LDS -> MLP=8), then pure FADD walk.
        {
            const int o2 = 2 * lane;
            const int cbase = wid * 8;
            if (cbase < valid) {
                int cnt = valid - cbase;
                if (cnt > 8) cnt = 8;
                float2 hv[8];
                #pragma unroll
                for (int j = 0; j < 8; j++)
                    hv[j] = (j < cnt)
                        ? *reinterpret_cast<const float2*>(h_sm + (cbase + j) * HSTRIDE + o2)
                        : make_float2(0.0f, 0.0f);
                int cur = batch_sm[cbase];
                float2 acc2 = make_float2(0.0f, 0.0f);
                #pragma unroll
                for (int j = 0; j < 8; j++) {
                    if (j >= cnt) break;
                    const int seg = batch_sm[cbase + j];  // LDS broadcast, warp-uniform
                    if (seg != cur) {                     // warp-uniform branch
                        atomicAdd(out_s + (size_t)cur * DOUT + o2,     acc2.x);
                        atomicAdd(out_s + (size_t)cur * DOUT + o2 + 1, acc2.y);
                        acc2.x = 0.0f; acc2.y = 0.0f;
                        cur = seg;
                    }
                    acc2.x += hv[j].x;
                    acc2.y += hv[j].y;
                }
                atomicAdd(out_s + (size_t)cur * DOUT + o2,     acc2.x);
                atomicAdd(out_s + (size_t)cur * DOUT + o2 + 1, acc2.y);
            }
        }
        // no trailing sync: h/batch double-buffered; staging rearm is ordered by
        // the single sync one iteration later (all GEMM reads precede that sync)
    }
}

// ---------------- relu + row-max normalize (consumes & re-zeroes scratch) ----------------
// 128 threads/block; each 16-lane half-warp owns one graph (64 f32 = 16 x float4).

__global__ void normalize_kernel(float* __restrict__ out, int nSeg)
{
    const int half = threadIdx.x >> 4;           // 0..7 half-warps per block
    const int hl   = threadIdx.x & 15;
    const int g    = blockIdx.x * 8 + half;
    if (g >= nSeg) return;
    const size_t base = (size_t)g * DOUT + hl * 4;
    float4 v = *reinterpret_cast<float4*>(g_scratch + base);
    *reinterpret_cast<float4*>(g_scratch + base) = make_float4(0.f, 0.f, 0.f, 0.f);
    v.x = fmaxf(v.x, 0.0f); v.y = fmaxf(v.y, 0.0f);
    v.z = fmaxf(v.z, 0.0f); v.w = fmaxf(v.w, 0.0f);
    float m = fmaxf(fmaxf(v.x, v.y), fmaxf(v.z, v.w));
    #pragma unroll
    for (int off = 8; off > 0; off >>= 1)
        m = fmaxf(m, __shfl_xor_sync(0xffffffff, m, off));
    float4 r;
    r.x = v.x / m; r.y = v.y / m; r.z = v.z / m; r.w = v.w / m;
    *reinterpret_cast<float4*>(out + base) = r;
}

// ---------------- launch ----------------

extern "C" void kernel_launch(void* const* d_in, const int* in_sizes, int n_in,
                              void* d_out, int out_size)
{
    const float* x     = (const float*)d_in[0];
    const float* W     = (const float*)d_in[1];
    const float* b     = (const float*)d_in[2];
    const int*   batch = (const int*)d_in[3];
    float* out = (float*)d_out;

    const int nAtoms = in_sizes[0] / DIN;
    const int nSeg   = out_size / DOUT;
    const int nTiles = (nAtoms + TILE - 1) / TILE;

    cudaFuncSetAttribute(fused_embed_segsum_kernel,
                         cudaFuncAttributeMaxDynamicSharedMemorySize, SMEM_TOTAL);

    int grid = 592;                    // 4 CTAs/SM, persistent
    if (grid > nTiles) grid = nTiles;

    fused_embed_segsum_kernel<<<grid, THREADS, SMEM_TOTAL>>>(
        x, W, b, batch, nAtoms, nTiles, nSeg);
    normalize_kernel<<<(nSeg + 7) / 8, 128>>>(out, nSeg);
}

// round 14
// speedup vs baseline: 1.1341x; 1.0352x over previous
#include <cuda_runtime.h>
#include <cuda_bf16.h>
#include <cstdint>

#define DIN        118
#define DOUT       64
#define TILE       32
#define THREADS    128
#define HSTRIDE    72        // floats per h row (padding vs bank conflicts)
#define XROW_BYTES 472       // 118 * 4
#define XTILE_B    (TILE * XROW_BYTES)   // 15104, 16B-multiple
#define NSTAGE     2
#define HTILE_B    (TILE * HSTRIDE * 4)  // 9216

// dynamic smem layout (bytes)
#define SM_H      0                       // f32 [2][32][72]          = 18432
#define SM_MBAR   18432                   // 2 x 8B mbarriers         = 16
#define SM_BSTG   18448                   // raw batch staging 2x128  = 256
#define SM_STG    18704                   // f32 staging 2 x 15104 (16B aligned)
#define SMEM_TOTAL (SM_STG + NSTAGE * XTILE_B)   // 48912  (4 CTAs = 195.6 KB)

// segment-sum scratch (consumed & re-zeroed by normalize -> graph-replay safe)
#define SCRATCH_CAP (1 << 20)             // 4 MB: supports nSeg <= 16384
__device__ float g_scratch[SCRATCH_CAP];

// ---------------- helpers ----------------

__device__ __forceinline__ uint32_t smem_to_u32(const void* p) {
    uint32_t a;
    asm("{ .reg .u64 t; cvta.to.shared.u64 t, %1; cvt.u32.u64 %0, t; }"
        : "=r"(a) : "l"(p));
    return a;
}

#define CVT_BF16X2(result, lo, hi) \
    asm("cvt.rn.satfinite.bf16x2.f32 %0, %1, %2;" : "=r"(result) : "f"(hi), "f"(lo))

#define MBARRIER_INIT(mbar, count) \
    asm volatile("mbarrier.init.shared.b64 [%0], %1;" \
                 :: "r"((uint32_t)(mbar)), "r"((uint32_t)(count)) : "memory")

#define MBARRIER_EXPECT_TX(mbar, tx_bytes) \
    asm volatile("mbarrier.arrive.expect_tx.shared.b64 _, [%0], %1;" \
                 :: "r"((uint32_t)(mbar)), "r"((uint32_t)(tx_bytes)) : "memory")

#define MBARRIER_WAIT_PARITY(mbar, parity) do {                                   \
    uint32_t _m = (uint32_t)(mbar);                                               \
    uint32_t _p = (uint32_t)(parity);                                             \
    uint32_t _done;                                                               \
    asm volatile("{\n\t.reg .pred p;\n\t"                                         \
        "mbarrier.try_wait.parity.acquire.cta.shared::cta.b64 p, [%1], %2;\n\t"   \
        "selp.b32 %0, 1, 0, p;\n\t}"                                              \
        : "=r"(_done) : "r"(_m), "r"(_p) : "memory");                             \
    if (!_done) {                                                                 \
        asm volatile("{\n\t.reg .pred P1;\n\t"                                    \
            "WAIT_LOOP_%=:\n\t"                                                   \
            "mbarrier.try_wait.parity.acquire.cta.shared::cta.b64 P1, [%0], %1, 0x989680;\n\t" \
            "@P1 bra.uni WAIT_DONE_%=;\n\t"                                       \
            "bra.uni WAIT_LOOP_%=;\n\t"                                           \
            "WAIT_DONE_%=:\n\t}"                                                  \
            :: "r"(_m), "r"(_p) : "memory");                                      \
    }                                                                             \
} while (0)

// single bulk async copy: global -> shared, completion via mbarrier tx-bytes
#define CP_BULK(dst_smem, src_gmem, nbytes, mbar) \
    asm volatile("cp.async.bulk.shared::cluster.global.mbarrier::complete_tx::bytes " \
                 "[%0], [%1], %2, [%3];" \
                 :: "r"((uint32_t)(dst_smem)), "l"(src_gmem), \
                    "r"((uint32_t)(nbytes)), "r"((uint32_t)(mbar)) : "memory")

__device__ __forceinline__ void mma16816(float* d, uint32_t a0, uint32_t a1, uint32_t a2,
                                         uint32_t a3, uint32_t b0, uint32_t b1) {
    asm volatile("mma.sync.aligned.m16n8k16.row.col.f32.bf16.bf16.f32 "
                 "{%0,%1,%2,%3}, {%4,%5,%6,%7}, {%8,%9}, {%0,%1,%2,%3};"
                 : "+f"(d[0]), "+f"(d[1]), "+f"(d[2]), "+f"(d[3])
                 : "r"(a0), "r"(a1), "r"(a2), "r"(a3), "r"(b0), "r"(b1));
}

// issue bulk copies (x tile + batch ids) for one tile into staging buffer `buf`
__device__ __forceinline__ void issue_tile(const char* xbase, const char* bbase,
                                           uint32_t smem_u, int buf,
                                           int tile, int nAtoms)
{
    int valid = nAtoms - tile * TILE;
    if (valid > TILE) valid = TILE;
    const uint32_t xb16 = (uint32_t)(valid * XROW_BYTES) & ~15u;
    const uint32_t bb16 = (uint32_t)(valid * 4) & ~15u;
    const uint32_t mb = smem_u + SM_MBAR + 8u * (uint32_t)buf;
    MBARRIER_EXPECT_TX(mb, xb16 + bb16);
    CP_BULK(smem_u + SM_STG + buf * XTILE_B,
            xbase + (size_t)tile * XTILE_B, xb16, mb);
    if (bb16)
        CP_BULK(smem_u + SM_BSTG + buf * 128,
                bbase + (size_t)tile * TILE * 4, bb16, mb);
}

// ---------------- main fused kernel ----------------

__global__ void __launch_bounds__(THREADS, 4)
fused_embed_segsum_kernel(const float* __restrict__ x,
                          const float* __restrict__ W,
                          const float* __restrict__ bias_v,
                          const int*   __restrict__ batch,    // int32
                          int nAtoms, int nTiles, int nSeg)
{
    extern __shared__ char smem[];
    const uint32_t smem_u = smem_to_u32(smem);
    const int tid  = threadIdx.x;
    const int wid  = tid >> 5;    // 0..3
    const int lane = tid & 31;

    const char* xbase = reinterpret_cast<const char*>(x);
    const char* bbase = reinterpret_cast<const char*>(batch);
    float* out_s = g_scratch;

    int segCap = nSeg;
    if (segCap * DOUT > SCRATCH_CAP) segCap = SCRATCH_CAP / DOUT;

    // ---- init mbarriers; issue copy of first tile into buf 0 ----
    if (tid == 0) {
        MBARRIER_INIT(smem_u + SM_MBAR, 1);
        MBARRIER_INIT(smem_u + SM_MBAR + 8, 1);
    }
    __syncthreads();

    const int t0 = blockIdx.x;
    if (tid == 0 && t0 < nTiles)
        issue_tile(xbase, bbase, smem_u, 0, t0, nAtoms);

    // warp tiling: rows (wid&1)*16, cols (wid>>1)*32
    const int m0    = (wid & 1) * 16;
    const int nbase = (wid >> 1) * 32;

    // ---- W fragments straight from global (canonical m16n8k16 B layout) ----
    uint32_t bf[8][8];   // [ks][j*2 + {lo,hi}]
    {
        const int kcw = 2 * (lane & 3);
        #pragma unroll
        for (int ks = 0; ks < 8; ks++) {
            const int k0 = 16 * ks + kcw;
            const int k1 = k0 + 8;
            #pragma unroll
            for (int j = 0; j < 4; j++) {
                const int n = nbase + j * 8 + (lane >> 2);
                const float* wr = W + (size_t)n * DIN;
                uint32_t lo = 0, hi = 0;
                if (k0 < DIN) { float2 v = *reinterpret_cast<const float2*>(wr + k0); CVT_BF16X2(lo, v.x, v.y); }
                if (k1 < DIN) { float2 v = *reinterpret_cast<const float2*>(wr + k1); CVT_BF16X2(hi, v.x, v.y); }
                bf[ks][j * 2]     = lo;
                bf[ks][j * 2 + 1] = hi;
            }
        }
    }

    // per-lane bias for cols nbase + nt*8 + 2*(lane&3) + {0,1}
    float2 bv[4];
    {
        const int c0 = nbase + 2 * (lane & 3);
        #pragma unroll
        for (int nt = 0; nt < 4; nt++)
            bv[nt] = *reinterpret_cast<const float2*>(bias_v + nt * 8 + c0);
    }

    // A-fragment row/col bases (row-major A, m16n8k16)
    const int rA0 = m0 + (lane >> 2);
    const int rA1 = rA0 + 8;
    const int kc  = 2 * (lane & 3);

    int it = 0;
    for (int t = t0; t < nTiles; t += gridDim.x, it++) {
        const int row0 = t * TILE;
        int valid = nAtoms - row0;
        if (valid > TILE) valid = TILE;
        const int buf = it & 1;
        float* h_sm = reinterpret_cast<float*>(smem + SM_H + buf * HTILE_B);
        const float* stg_f = reinterpret_cast<const float*>(smem + SM_STG + buf * XTILE_B);
        const int* bstg = reinterpret_cast<const int*>(smem + SM_BSTG + buf * 128);

        // the ONE per-tile CTA barrier: all warps finished last iteration's
        // GEMM reads of buf^1 staging and h/epilogue work before we rearm it
        __syncthreads();

        // 1) issue copy of NEXT tile into the other buffer
        const int tn = t + gridDim.x;
        if (tid == 0 && tn < nTiles)
            issue_tile(xbase, bbase, smem_u, buf ^ 1, tn, nAtoms);

        // 2) wait for CURRENT tile's copies (per-thread acquire)
        MBARRIER_WAIT_PARITY(smem_u + SM_MBAR + 8u * (uint32_t)buf, (it >> 1) & 1);
        if (valid * XROW_BYTES & 15) {        // uniform; never taken when N%32==0
            if (tid == 0) {
                const int off = (valid * XROW_BYTES) & ~15;
                float2 v = *reinterpret_cast<const float2*>(
                    xbase + (size_t)row0 * XROW_BYTES + off);
                *reinterpret_cast<float2*>(const_cast<float*>(stg_f) + off / 4) = v;
            }
            __syncthreads();
        }

        // 3) GEMM: A fragments from f32 staging (LDS.64 + cvt), B from regs
        const bool rv0 = rA0 < valid;
        const bool rv1 = rA1 < valid;
        const float* pA0 = stg_f + rA0 * DIN;
        const float* pA1 = stg_f + rA1 * DIN;

        float acc[4][4];
        #pragma unroll
        for (int nt = 0; nt < 4; nt++)
            #pragma unroll
            for (int i = 0; i < 4; i++) acc[nt][i] = 0.0f;

        #pragma unroll
        for (int ks = 0; ks < 8; ks++) {
            const int k0 = 16 * ks + kc;
            const int k1 = k0 + 8;
            uint32_t a0 = 0, a1 = 0, a2 = 0, a3 = 0;
            if (rv0 && k0 < DIN) { float2 v = *reinterpret_cast<const float2*>(pA0 + k0); CVT_BF16X2(a0, v.x, v.y); }
            if (rv1 && k0 < DIN) { float2 v = *reinterpret_cast<const float2*>(pA1 + k0); CVT_BF16X2(a1, v.x, v.y); }
            if (rv0 && k1 < DIN) { float2 v = *reinterpret_cast<const float2*>(pA0 + k1); CVT_BF16X2(a2, v.x, v.y); }
            if (rv1 && k1 < DIN) { float2 v = *reinterpret_cast<const float2*>(pA1 + k1); CVT_BF16X2(a3, v.x, v.y); }
            mma16816(acc[0], a0, a1, a2, a3, bf[ks][0], bf[ks][1]);
            mma16816(acc[1], a0, a1, a2, a3, bf[ks][2], bf[ks][3]);
            mma16816(acc[2], a0, a1, a2, a3, bf[ks][4], bf[ks][5]);
            mma16816(acc[3], a0, a1, a2, a3, bf[ks][6], bf[ks][7]);
        }

        // 4) segment reduction.
        //    Fast path (~88% of tiles): full tile, single segment -> pure
        //    register shuffle reduction, no smem, no barrier.
        //    CTA-uniform decision: every warp computes it from the same bstg.
        bool uniformTile = false;
        int  myseg = 0;
        if (valid == TILE) {
            int raw = bstg[lane];
            myseg = raw < 0 ? 0 : (raw >= segCap ? segCap - 1 : raw);
            const int s0 = __shfl_sync(0xffffffffu, myseg, 0);
            uniformTile = __all_sync(0xffffffffu, myseg == s0);
        }

        if (uniformTile) {
            const int seg = __shfl_sync(0xffffffffu, myseg, 0);
            float2 s[4];
            #pragma unroll
            for (int nt = 0; nt < 4; nt++) {
                const float h0 = fmaxf(acc[nt][0] + bv[nt].x, 0.0f);
                const float h1 = fmaxf(acc[nt][1] + bv[nt].y, 0.0f);
                const float h2 = fmaxf(acc[nt][2] + bv[nt].x, 0.0f);
                const float h3 = fmaxf(acc[nt][3] + bv[nt].y, 0.0f);
                s[nt] = make_float2(h0 + h2, h1 + h3);   // rows rA0 + rA1
            }
            // sum over lane bits 2..4 (rows m0..m0+7 within each col group)
            #pragma unroll
            for (int mask = 4; mask <= 16; mask <<= 1) {
                #pragma unroll
                for (int nt = 0; nt < 4; nt++) {
                    s[nt].x += __shfl_xor_sync(0xffffffffu, s[nt].x, mask);
                    s[nt].y += __shfl_xor_sync(0xffffffffu, s[nt].y, mask);
                }
            }
            const int q4 = lane >> 2;
            if (q4 < 4) {
                const int col = nbase + q4 * 8 + 2 * (lane & 3);
                atomicAdd(out_s + (size_t)seg * DOUT + col,     s[q4].x);
                atomicAdd(out_s + (size_t)seg * DOUT + col + 1, s[q4].y);
            }
        } else {
            // slow path: h round trip through smem + run-length walk
            {
                const int rbase = m0 + (lane >> 2);
                const int c0 = nbase + 2 * (lane & 3);
                #pragma unroll
                for (int nt = 0; nt < 4; nt++) {
                    float2 h0, h1;
                    h0.x = fmaxf(acc[nt][0] + bv[nt].x, 0.0f);
                    h0.y = fmaxf(acc[nt][1] + bv[nt].y, 0.0f);
                    h1.x = fmaxf(acc[nt][2] + bv[nt].x, 0.0f);
                    h1.y = fmaxf(acc[nt][3] + bv[nt].y, 0.0f);
                    *reinterpret_cast<float2*>(h_sm + rbase * HSTRIDE + nt * 8 + c0) = h0;
                    *reinterpret_cast<float2*>(h_sm + (rbase + 8) * HSTRIDE + nt * 8 + c0) = h1;
                }
            }
            __syncthreads();

            const int bLim = (valid * 4) & ~15;
            const int o2 = 2 * lane;
            const int cbase = wid * 8;
            if (cbase < valid) {
                int cnt = valid - cbase;
                if (cnt > 8) cnt = 8;
                float2 hv[8];
                #pragma unroll
                for (int j = 0; j < 8; j++)
                    hv[j] = (j < cnt)
                        ? *reinterpret_cast<const float2*>(h_sm + (cbase + j) * HSTRIDE + o2)
                        : make_float2(0.0f, 0.0f);
                int cur;
                {
                    int raw = (((cbase + 1) * 4) <= bLim) ? bstg[cbase] : batch[row0 + cbase];
                    cur = raw < 0 ? 0 : (raw >= segCap ? segCap - 1 : raw);
                }
                float2 acc2 = make_float2(0.0f, 0.0f);
                #pragma unroll
                for (int j = 0; j < 8; j++) {
                    if (j >= cnt) break;
                    const int c = cbase + j;
                    int raw = (((c + 1) * 4) <= bLim) ? bstg[c] : batch[row0 + c];
                    const int seg = raw < 0 ? 0 : (raw >= segCap ? segCap - 1 : raw);
                    if (seg != cur) {                     // warp-uniform branch
                        atomicAdd(out_s + (size_t)cur * DOUT + o2,     acc2.x);
                        atomicAdd(out_s + (size_t)cur * DOUT + o2 + 1, acc2.y);
                        acc2.x = 0.0f; acc2.y = 0.0f;
                        cur = seg;
                    }
                    acc2.x += hv[j].x;
                    acc2.y += hv[j].y;
                }
                atomicAdd(out_s + (size_t)cur * DOUT + o2,     acc2.x);
                atomicAdd(out_s + (size_t)cur * DOUT + o2 + 1, acc2.y);
            }
        }
    }
}

// ---------------- relu + row-max normalize (consumes & re-zeroes scratch) ----------------
// 128 threads/block; each 16-lane half-warp owns TWO graphs (ILP=2 loads).

__global__ void normalize_kernel(float* __restrict__ out, int nSeg)
{
    const int half = threadIdx.x >> 4;           // 0..7 half-warps per block
    const int hl   = threadIdx.x & 15;
    const int g0   = (blockIdx.x * 8 + half) * 2;
    if (g0 >= nSeg) return;
    const bool has1 = (g0 + 1) < nSeg;
    const size_t b0 = (size_t)g0 * DOUT + hl * 4;
    const size_t b1 = b0 + DOUT;

    float4 v0 = *reinterpret_cast<float4*>(g_scratch + b0);
    float4 v1 = has1 ? *reinterpret_cast<float4*>(g_scratch + b1)
                     : make_float4(0.f, 0.f, 0.f, 0.f);
    *reinterpret_cast<float4*>(g_scratch + b0) = make_float4(0.f, 0.f, 0.f, 0.f);
    if (has1) *reinterpret_cast<float4*>(g_scratch + b1) = make_float4(0.f, 0.f, 0.f, 0.f);

    v0.x = fmaxf(v0.x, 0.f); v0.y = fmaxf(v0.y, 0.f);
    v0.z = fmaxf(v0.z, 0.f); v0.w = fmaxf(v0.w, 0.f);
    v1.x = fmaxf(v1.x, 0.f); v1.y = fmaxf(v1.y, 0.f);
    v1.z = fmaxf(v1.z, 0.f); v1.w = fmaxf(v1.w, 0.f);

    float m0 = fmaxf(fmaxf(v0.x, v0.y), fmaxf(v0.z, v0.w));
    float m1 = fmaxf(fmaxf(v1.x, v1.y), fmaxf(v1.z, v1.w));
    #pragma unroll
    for (int off = 8; off > 0; off >>= 1) {
        m0 = fmaxf(m0, __shfl_xor_sync(0xffffffff, m0, off));
        m1 = fmaxf(m1, __shfl_xor_sync(0xffffffff, m1, off));
    }

    float4 r0, r1;
    r0.x = v0.x / m0; r0.y = v0.y / m0; r0.z = v0.z / m0; r0.w = v0.w / m0;
    *reinterpret_cast<float4*>(out + b0) = r0;
    if (has1) {
        r1.x = v1.x / m1; r1.y = v1.y / m1; r1.z = v1.z / m1; r1.w = v1.w / m1;
        *reinterpret_cast<float4*>(out + b1) = r1;
    }
}

// ---------------- launch ----------------

extern "C" void kernel_launch(void* const* d_in, const int* in_sizes, int n_in,
                              void* d_out, int out_size)
{
    const float* x     = (const float*)d_in[0];
    const float* W     = (const float*)d_in[1];
    const float* b     = (const float*)d_in[2];
    const int*   batch = (const int*)d_in[3];
    float* out = (float*)d_out;

    const int nAtoms = in_sizes[0] / DIN;
    const int nSeg   = out_size / DOUT;
    const int nTiles = (nAtoms + TILE - 1) / TILE;

    cudaFuncSetAttribute(fused_embed_segsum_kernel,
                         cudaFuncAttributeMaxDynamicSharedMemorySize, SMEM_TOTAL);

    int grid = 592;                    // 4 CTAs/SM, persistent
    if (grid > nTiles) grid = nTiles;

    fused_embed_segsum_kernel<<<grid, THREADS, SMEM_TOTAL>>>(
        x, W, b, batch, nAtoms, nTiles, nSeg);
    normalize_kernel<<<(nSeg + 15) / 16, 128>>>(out, nSeg);
}